// round 5
// baseline (speedup 1.0000x reference)
#include <cuda_runtime.h>

// Problem constants
#define Bn 16
#define Cn 512
#define Hn 80
#define Wn 80
#define HWn (Hn*Wn)          // 6400
#define CHWn (Cn*HWn)        // 3276800
#define TOTALn (Bn*CHWn)     // 52428800
#define NPIX (Bn*HWn)        // 102400

// K2: 256 threads x 64 contiguous elements = 16384 elements per block
//     16384 | CHWn (200 blocks per batch), and since 16384%64==0 and 6400%64==0,
//     a thread's 64-element run never crosses a plane boundary.
#define K2_TPB 256
#define K2_EPT 64
#define K2_EPB (K2_TPB*K2_EPT)     // 16384
#define NBLK2 (TOTALn/K2_EPB)      // 3200
#define CAP 256                    // max detections per K2 block (avg ~39)

// K3: scan 3200 counts, one block, 800 active threads x 4 counts (uint4)
#define K3_TPB 1024
#define K3_ACTIVE 800

// ---- scratch (allocation-free: __device__ globals) ----
__device__ unsigned int g_m[NPIX];               // per-pixel max of relu(x), float bits
__device__ unsigned int g_counts[NBLK2];
__device__ unsigned int g_offsets[NBLK2];
__device__ unsigned int g_scratch[NBLK2 * CAP];  // packed (h<<8)|w, block-ordered

// ---------------------------------------------------------------------------
// K0: init output padding only
__global__ void k0_init(float4* __restrict__ out4, int n4, int half4) {
    int i = blockIdx.x * blockDim.x + threadIdx.x;
    if (i < half4) {
        out4[i] = make_float4(-1.f, -1.f, -1.f, -1.f);       // grid padding
    } else if (i < n4) {
        out4[i] = make_float4(-4.5f, -4.5f, -4.5f, -4.5f);   // 8*(-1)+3.5
    }
}

// ---------------------------------------------------------------------------
// K1: per-pixel depthwise max of relu(x). One thread per pixel, 512 channels,
// 4 independent accumulators, streaming loads, direct write (no atomics).
__global__ void __launch_bounds__(256) k1_dwmax(const float* __restrict__ x) {
    int p = blockIdx.x * blockDim.x + threadIdx.x;
    if (p >= NPIX) return;
    int b  = p / HWn;
    int hw = p - b * HWn;
    const float* base = x + (size_t)b * CHWn + hw;
    float m0 = 0.f, m1 = 0.f, m2 = 0.f, m3 = 0.f;   // relu floor
    #pragma unroll 4
    for (int c = 0; c < Cn; c += 4) {
        m0 = fmaxf(m0, __ldcs(base + (size_t)(c+0) * HWn));
        m1 = fmaxf(m1, __ldcs(base + (size_t)(c+1) * HWn));
        m2 = fmaxf(m2, __ldcs(base + (size_t)(c+2) * HWn));
        m3 = fmaxf(m3, __ldcs(base + (size_t)(c+3) * HWn));
    }
    g_m[p] = __float_as_uint(fmaxf(fmaxf(m0, m1), fmaxf(m2, m3)));
}

// ---------------------------------------------------------------------------
// neighbor test: v (>=0) must be >= all in-bounds raw 3x3 neighbors. Rare path.
__device__ __noinline__ bool neigh_ok(const float* __restrict__ plane,
                                      float v, int h, int w) {
    #pragma unroll
    for (int dh = -1; dh <= 1; dh++) {
        int nh = h + dh;
        if (nh < 0 || nh >= Hn) continue;
        #pragma unroll
        for (int dw = -1; dw <= 1; dw++) {
            if (dh == 0 && dw == 0) continue;
            int nw = w + dw;
            if (nw < 0 || nw >= Wn) continue;
            if (v < plane[nh * Wn + nw]) return false;
        }
    }
    return true;
}

// ---------------------------------------------------------------------------
// K2: per-element predicate, 64 contiguous elements/thread. The block's whole
// g_m pixel plane (one batch, 6400 u32) is staged in smem; compares are exact
// 32-bit LDS. Ordered per-block compaction into scratch.
__global__ void __launch_bounds__(K2_TPB) k2_pred(const float* __restrict__ x) {
    __shared__ unsigned int sm[HWn];        // 25.6 KB: g_m plane for this batch
    __shared__ int ws[K2_TPB / 32];
    __shared__ int s_total;

    int blk = blockIdx.x;
    int t = threadIdx.x;
    int lane = t & 31;
    int warp = t >> 5;

    int e0 = blk * K2_EPB;                  // block start (multiple of 16384)
    int b  = e0 / CHWn;                     // whole block in one batch

    // stage g_m plane for batch b
    {
        const uint4* src = reinterpret_cast<const uint4*>(&g_m[b * HWn]);
        uint4* dst = reinterpret_cast<uint4*>(sm);
        for (int i = t; i < HWn / 4; i += K2_TPB) dst[i] = src[i];
    }
    __syncthreads();

    int et  = e0 + t * K2_EPT;              // this thread's first element
    int r   = et - b * CHWn;
    int c   = r / HWn;                      // single channel for all 64 elements
    int hw0 = r - c * HWn;                  // 64-aligned; hw0+63 < HWn (no wrap)

    const float* px = x + et;
    const float* plane = x + (size_t)b * CHWn + (size_t)c * HWn;

    // detection bits for 64 elements
    unsigned long long det = 0ull;
    #pragma unroll
    for (int g = 0; g < K2_EPT / 4; g++) {
        float4 xv = __ldcs(reinterpret_cast<const float4*>(px) + g);
        float v0 = fmaxf(xv.x, 0.f), v1 = fmaxf(xv.y, 0.f);
        float v2 = fmaxf(xv.z, 0.f), v3 = fmaxf(xv.w, 0.f);
        int i0 = 4 * g;
        if (__float_as_uint(v0) == sm[hw0 + i0 + 0]) det |= 1ull << (i0 + 0);
        if (__float_as_uint(v1) == sm[hw0 + i0 + 1]) det |= 1ull << (i0 + 1);
        if (__float_as_uint(v2) == sm[hw0 + i0 + 2]) det |= 1ull << (i0 + 2);
        if (__float_as_uint(v3) == sm[hw0 + i0 + 3]) det |= 1ull << (i0 + 3);
    }

    // rare: confirm 3x3 local max for candidates
    if (det) {
        unsigned long long dd = det;
        while (dd) {
            int i = __ffsll(dd) - 1;
            dd &= dd - 1;
            int hw = hw0 + i;
            int h = hw / Wn, w = hw - (hw / Wn) * Wn;
            float v = __uint_as_float(sm[hw]);
            if (!neigh_ok(plane, v, h, w)) det &= ~(1ull << i);
        }
    }
    int cnt = __popcll(det);

    // block scan (warp shuffles, 2 barriers)
    int incl = cnt;
    #pragma unroll
    for (int off = 1; off < 32; off <<= 1) {
        int n = __shfl_up_sync(0xFFFFFFFFu, incl, off);
        if (lane >= off) incl += n;
    }
    if (lane == 31) ws[warp] = incl;
    __syncthreads();
    if (t < K2_TPB / 32) {                  // 8 lanes of warp 0
        int v = ws[t];
        int iv = v;
        #pragma unroll
        for (int off = 1; off < K2_TPB / 32; off <<= 1) {
            int n = __shfl_up_sync(0x000000FFu, iv, off);
            if (t >= off) iv += n;
        }
        ws[t] = iv - v;
        if (t == K2_TPB / 32 - 1) s_total = iv;
    }
    __syncthreads();

    int o = ws[warp] + (incl - cnt);
    unsigned int* dst = g_scratch + (size_t)blk * CAP;
    unsigned long long dd = det;
    while (dd) {
        int i = __ffsll(dd) - 1;
        dd &= dd - 1;
        int hw = hw0 + i;
        int h = hw / Wn, w = hw - (hw / Wn) * Wn;
        if (o < CAP) dst[o] = (unsigned)((h << 8) | w);
        o++;
    }
    if (t == 0) g_counts[blk] = (unsigned)min(s_total, CAP);
}

// ---------------------------------------------------------------------------
// K3: exclusive scan of 3200 block counts; 800 active threads x 4 (one uint4).
__global__ void __launch_bounds__(K3_TPB) k3_scan() {
    int t = threadIdx.x;
    int lane = t & 31;
    int warp = t >> 5;
    unsigned int l0=0, l1=0, l2=0, l3=0, sum=0;
    if (t < K3_ACTIVE) {
        uint4 v = reinterpret_cast<const uint4*>(g_counts)[t];
        l0 = v.x; l1 = v.y; l2 = v.z; l3 = v.w;
        sum = l0 + l1 + l2 + l3;
    }
    unsigned int incl = sum;
    #pragma unroll
    for (int off = 1; off < 32; off <<= 1) {
        unsigned int n = __shfl_up_sync(0xFFFFFFFFu, incl, off);
        if (lane >= off) incl += n;
    }
    __shared__ unsigned int ws[K3_TPB / 32];
    if (lane == 31) ws[warp] = incl;
    __syncthreads();
    if (t < K3_TPB / 32) {
        unsigned int v = ws[t];
        unsigned int iv = v;
        #pragma unroll
        for (int off = 1; off < 32; off <<= 1) {
            unsigned int n = __shfl_up_sync(0xFFFFFFFFu, iv, off);
            if (t >= off) iv += n;
        }
        ws[t] = iv - v;
    }
    __syncthreads();
    if (t < K3_ACTIVE) {
        unsigned int run = ws[warp] + (incl - sum);
        uint4 o;
        o.x = run;            run += l0;
        o.y = run;            run += l1;
        o.z = run;            run += l2;
        o.w = run;
        reinterpret_cast<uint4*>(g_offsets)[t] = o;
    }
}

// ---------------------------------------------------------------------------
// K4: scatter scratch records to final output.
__global__ void __launch_bounds__(CAP) k4_scatter(float* __restrict__ out, int nmax) {
    int blk = blockIdx.x;
    unsigned int cnt = g_counts[blk];
    int t = threadIdx.x;
    if (t < (int)cnt) {
        unsigned int n = g_offsets[blk] + (unsigned)t;
        if (n < (unsigned)nmax) {
            unsigned int pk = g_scratch[(size_t)blk * CAP + t];
            float h = (float)(pk >> 8);
            float w = (float)(pk & 0xFF);
            out[2u*n + 0u] = h;
            out[2u*n + 1u] = w;
            float* kp = out + 2u * (unsigned)nmax;
            kp[2u*n + 0u] = 8.0f * h + 3.5f;   // ((p*2+.5)*2+.5)*2+.5
            kp[2u*n + 1u] = 8.0f * w + 3.5f;
        }
    }
}

// ---------------------------------------------------------------------------
extern "C" void kernel_launch(void* const* d_in, const int* in_sizes, int n_in,
                              void* d_out, int out_size) {
    const float* x = (const float*)d_in[0];
    float* out = (float*)d_out;
    int nmax = out_size / 4;

    {   // K0: output padding (float4)
        int n4 = out_size / 4;
        int half4 = (out_size / 2) / 4;
        k0_init<<<(n4 + 255) / 256, 256>>>((float4*)out, n4, half4);
    }
    k1_dwmax<<<(NPIX + 255) / 256, 256>>>(x);   // depthwise relu-max, no atomics
    k2_pred<<<NBLK2, K2_TPB>>>(x);              // smem-plane compare + compaction
    k3_scan<<<1, K3_TPB>>>();                   // scan 3200 counts
    k4_scatter<<<NBLK2, CAP>>>(out, nmax);
}

// round 6
// speedup vs baseline: 1.4264x; 1.4264x over previous
#include <cuda_runtime.h>

// Problem constants
#define Bn 16
#define Cn 512
#define Hn 80
#define Wn 80
#define HWn (Hn*Wn)          // 6400
#define CHWn (Cn*HWn)        // 3276800
#define TOTALn (Bn*CHWn)     // 52428800
#define NPIX (Bn*HWn)        // 102400

// K2: 256 threads x 16 contiguous elements = 4096 elements per block
#define K2_TPB 256
#define K2_EPT 16
#define K2_EPB (K2_TPB*K2_EPT)     // 4096
#define NBLK2 (TOTALn/K2_EPB)      // 12800
#define CAP 64                     // max detections per K2 block (avg ~8)

// K3: two-level scan of 12800 counts: 16 blocks x 800 counts, then 16 bases
#define K3_SB 16
#define K3_PER_SB (NBLK2/K3_SB)    // 800

// ---- scratch (allocation-free: __device__ globals) ----
__device__ unsigned int   g_m[NPIX];              // per-pixel max of relu(x), float bits
__device__ unsigned short g_m16[NPIX];            // top 16 bits of g_m (prefilter)
__device__ unsigned int   g_counts[NBLK2];
__device__ unsigned int   g_offsets[NBLK2];       // exclusive WITHIN superblock
__device__ unsigned int   g_bsum[K3_SB];
__device__ unsigned int   g_bbase[K3_SB];         // exclusive superblock bases
__device__ unsigned int   g_scratch[NBLK2 * CAP]; // packed (h<<8)|w, block-ordered

// ---------------------------------------------------------------------------
// K0: init output padding only
__global__ void k0_init(float4* __restrict__ out4, int n4, int half4) {
    int i = blockIdx.x * blockDim.x + threadIdx.x;
    if (i < half4) {
        out4[i] = make_float4(-1.f, -1.f, -1.f, -1.f);       // grid padding
    } else if (i < n4) {
        out4[i] = make_float4(-4.5f, -4.5f, -4.5f, -4.5f);   // 8*(-1)+3.5
    }
}

// ---------------------------------------------------------------------------
// K1: per-pixel depthwise max of relu(x). One thread per pixel, 512 channels.
// Plain loads (proven), but 4 independent accumulators to break the fmax chain.
__global__ void __launch_bounds__(256) k1_dwmax(const float* __restrict__ x) {
    int p = blockIdx.x * blockDim.x + threadIdx.x;
    if (p >= NPIX) return;
    int b  = p / HWn;
    int hw = p - b * HWn;
    const float* base = x + (size_t)b * CHWn + hw;
    float m0 = 0.f, m1 = 0.f, m2 = 0.f, m3 = 0.f;   // relu floor
    #pragma unroll 8
    for (int c = 0; c < Cn; c += 4) {
        m0 = fmaxf(m0, base[(size_t)(c+0) * HWn]);
        m1 = fmaxf(m1, base[(size_t)(c+1) * HWn]);
        m2 = fmaxf(m2, base[(size_t)(c+2) * HWn]);
        m3 = fmaxf(m3, base[(size_t)(c+3) * HWn]);
    }
    unsigned int mb = __float_as_uint(fmaxf(fmaxf(m0, m1), fmaxf(m2, m3)));
    g_m[p]   = mb;
    g_m16[p] = (unsigned short)(mb >> 16);
}

// ---------------------------------------------------------------------------
// neighbor test: v (>=0) must be >= all in-bounds raw 3x3 neighbors. Rare path.
__device__ __noinline__ bool neigh_ok(const float* __restrict__ plane,
                                      float v, int h, int w) {
    #pragma unroll
    for (int dh = -1; dh <= 1; dh++) {
        int nh = h + dh;
        if (nh < 0 || nh >= Hn) continue;
        #pragma unroll
        for (int dw = -1; dw <= 1; dw++) {
            if (dh == 0 && dw == 0) continue;
            int nw = w + dw;
            if (nw < 0 || nw >= Wn) continue;
            if (v < plane[nh * Wn + nw]) return false;
        }
    }
    return true;
}

// ---------------------------------------------------------------------------
// K2: per-element predicate, 16 contiguous elements/thread. 16-bit prefilter on
// g_m16, exact g_m check only on prefilter hit. Ordered per-block compaction.
// (Byte-identical to the 115.2us R4 version.)
__global__ void __launch_bounds__(K2_TPB) k2_pred(const float* __restrict__ x) {
    int blk = blockIdx.x;
    int t = threadIdx.x;
    int lane = t & 31;
    int warp = t >> 5;
    int e0 = blk * K2_EPB + t * K2_EPT;   // 16-aligned; within one (b,c,h) row

    int b  = e0 / CHWn;
    int r  = e0 - b * CHWn;
    int c  = r / HWn;
    int hw = r - c * HWn;
    int h  = hw / Wn;
    int w0 = hw - h * Wn;                 // multiple of 16

    const float* px = x + e0;
    int pix0 = b * HWn + h * Wn + w0;
    const unsigned short* pm16 = &g_m16[pix0];
    const float* plane = x + (size_t)b * CHWn + (size_t)c * HWn;

    unsigned int det = 0;
    #pragma unroll
    for (int g = 0; g < 2; g++) {
        float4 xa = reinterpret_cast<const float4*>(px)[2*g + 0];
        float4 xb = reinterpret_cast<const float4*>(px)[2*g + 1];
        uint4  m16 = reinterpret_cast<const uint4*>(pm16)[g];
        float v[8];
        v[0] = fmaxf(xa.x, 0.f); v[1] = fmaxf(xa.y, 0.f);
        v[2] = fmaxf(xa.z, 0.f); v[3] = fmaxf(xa.w, 0.f);
        v[4] = fmaxf(xb.x, 0.f); v[5] = fmaxf(xb.y, 0.f);
        v[6] = fmaxf(xb.z, 0.f); v[7] = fmaxf(xb.w, 0.f);
        unsigned int mw[4] = {m16.x, m16.y, m16.z, m16.w};
        #pragma unroll
        for (int i = 0; i < 8; i++) {
            unsigned int t16 = (mw[i >> 1] >> ((i & 1) * 16)) & 0xFFFFu;
            if ((__float_as_uint(v[i]) >> 16) == t16) {
                int wi = w0 + 8*g + i;
                if (__float_as_uint(v[i]) == g_m[pix0 + 8*g + i] &&
                    neigh_ok(plane, v[i], h, wi)) {
                    det |= 1u << (8*g + i);
                }
            }
        }
    }
    int cnt = __popc(det);

    // block scan via warp shuffles (2 barriers)
    int incl = cnt;
    #pragma unroll
    for (int off = 1; off < 32; off <<= 1) {
        int n = __shfl_up_sync(0xFFFFFFFFu, incl, off);
        if (lane >= off) incl += n;
    }
    __shared__ int ws[K2_TPB / 32];
    __shared__ int s_total;
    if (lane == 31) ws[warp] = incl;
    __syncthreads();
    if (t < K2_TPB / 32) {                 // 8 lanes of warp 0
        int v = ws[t];
        int iv = v;
        #pragma unroll
        for (int off = 1; off < K2_TPB / 32; off <<= 1) {
            int n = __shfl_up_sync(0x000000FFu, iv, off);
            if (t >= off) iv += n;
        }
        ws[t] = iv - v;
        if (t == K2_TPB / 32 - 1) s_total = iv;
    }
    __syncthreads();

    int o = ws[warp] + (incl - cnt);
    unsigned int* dst = g_scratch + (size_t)blk * CAP;
    unsigned int dd = det;
    while (dd) {
        int i = __ffs(dd) - 1;
        dd &= dd - 1;
        if (o < CAP) dst[o] = (unsigned)((h << 8) | (w0 + i));
        o++;
    }
    if (t == 0) g_counts[blk] = (unsigned)min(s_total, CAP);
}

// ---------------------------------------------------------------------------
// K3a: 16 blocks; each scans 800 counts (1/thread) -> local exclusive offsets
// + superblock sum.
__global__ void __launch_bounds__(1024) k3a_scan() {
    int sb = blockIdx.x;
    int t = threadIdx.x;
    int lane = t & 31;
    int warp = t >> 5;                      // 25 active warps (t < 800)
    unsigned int v = (t < K3_PER_SB) ? g_counts[sb * K3_PER_SB + t] : 0u;
    unsigned int incl = v;
    #pragma unroll
    for (int off = 1; off < 32; off <<= 1) {
        unsigned int n = __shfl_up_sync(0xFFFFFFFFu, incl, off);
        if (lane >= off) incl += n;
    }
    __shared__ unsigned int ws[32];
    if (lane == 31) ws[warp] = incl;
    __syncthreads();
    if (t < 32) {
        unsigned int w = ws[t];
        unsigned int iw = w;
        #pragma unroll
        for (int off = 1; off < 32; off <<= 1) {
            unsigned int n = __shfl_up_sync(0xFFFFFFFFu, iw, off);
            if (t >= off) iw += n;
        }
        ws[t] = iw - w;                     // exclusive warp base
        if (t == 31) g_bsum[sb] = iw;       // superblock total
    }
    __syncthreads();
    if (t < K3_PER_SB) g_offsets[sb * K3_PER_SB + t] = ws[warp] + (incl - v);
}

// K3b: one warp scans the 16 superblock sums into exclusive bases.
__global__ void k3b_base() {
    int t = threadIdx.x;                    // 32 threads
    unsigned int v = (t < K3_SB) ? g_bsum[t] : 0u;
    unsigned int incl = v;
    #pragma unroll
    for (int off = 1; off < 32; off <<= 1) {
        unsigned int n = __shfl_up_sync(0xFFFFFFFFu, incl, off);
        if (t >= off) incl += n;
    }
    if (t < K3_SB) g_bbase[t] = incl - v;
}

// ---------------------------------------------------------------------------
// K4: scatter scratch records to final output (adds superblock base).
__global__ void __launch_bounds__(CAP) k4_scatter(float* __restrict__ out, int nmax) {
    int blk = blockIdx.x;
    unsigned int cnt = g_counts[blk];
    int t = threadIdx.x;
    if (t < (int)cnt) {
        unsigned int n = g_bbase[blk / K3_PER_SB] + g_offsets[blk] + (unsigned)t;
        if (n < (unsigned)nmax) {
            unsigned int pk = g_scratch[(size_t)blk * CAP + t];
            float h = (float)(pk >> 8);
            float w = (float)(pk & 0xFF);
            out[2u*n + 0u] = h;
            out[2u*n + 1u] = w;
            float* kp = out + 2u * (unsigned)nmax;
            kp[2u*n + 0u] = 8.0f * h + 3.5f;   // ((p*2+.5)*2+.5)*2+.5
            kp[2u*n + 1u] = 8.0f * w + 3.5f;
        }
    }
}

// ---------------------------------------------------------------------------
extern "C" void kernel_launch(void* const* d_in, const int* in_sizes, int n_in,
                              void* d_out, int out_size) {
    const float* x = (const float*)d_in[0];
    float* out = (float*)d_out;
    int nmax = out_size / 4;

    {   // K0: output padding (float4)
        int n4 = out_size / 4;
        int half4 = (out_size / 2) / 4;
        k0_init<<<(n4 + 255) / 256, 256>>>((float4*)out, n4, half4);
    }
    k1_dwmax<<<(NPIX + 255) / 256, 256>>>(x);   // depthwise relu-max, 4 accumulators
    k2_pred<<<NBLK2, K2_TPB>>>(x);              // prefiltered predicate + compaction
    k3a_scan<<<K3_SB, 1024>>>();                // per-superblock scans (parallel)
    k3b_base<<<1, 32>>>();                      // 16 superblock bases
    k4_scatter<<<NBLK2, CAP>>>(out, nmax);
}